// round 5
// baseline (speedup 1.0000x reference)
#include <cuda_runtime.h>
#include <math.h>

#define NN 50000
#define EE 400000
#define FE_DIM 64
#define HD 128
#define NL 3
#define NB 16

// ---------------- scratch (static device globals; no allocation) ----------------
__device__ alignas(16) float g_x[NN * HD];             // node features (updated per layer)
__device__ alignas(16) float g_tmp[NN * HD];           // GEMM outputs
__device__ alignas(16) float g_agg[NN * 4 * HD];       // per-head aggregated x (input space)
__device__ alignas(16) float g_alE[EE * 12];           // per-edge attention logits, 3 layers x 4 heads
__device__ alignas(16) float g_alE_sum[12];
__device__ alignas(16) float g_alE_loop[12];           // self-loop edge logits (mean over E)
__device__ alignas(16) float g_als[NN * 4];
__device__ alignas(16) float g_ald[NN * 4];
__device__ int g_deg[NN];
__device__ int g_off[NN + 1];
__device__ int g_cur[NN];
__device__ int g_eid[EE];
__device__ int g_gs[NB + 1];
__device__ alignas(16) float g_Vs[NL * HD * 4];
__device__ alignas(16) float g_Vd[NL * HD * 4];
__device__ alignas(16) float g_Ve[NL * HD * 4];
__device__ alignas(16) float g_Fe[FE_DIM * 12];
__device__ alignas(16) float g_be[12];
__device__ alignas(16) float g_Wb[NL * 512 * HD];      // 0.25 * W_gat, reindexed [k=h*128+c][c']

// ---------------- init ----------------
__global__ void k_init() {
    int i = blockIdx.x * blockDim.x + threadIdx.x;
    if (i < NN) g_deg[i] = 0;
    if (i < 12) g_alE_sum[i] = 0.f;
}

// ---------------- fold attention vectors ----------------
// Vs[l][c][h] = sum_k W_gat[l][c][h*128+k] * att_src[l][h][k]   (Vd, Ve analogous)
// Fe[f][l*4+h] = sum_c W_ep[f][c] * Ve[l][c][h];   be[l*4+h] = sum_c b_ep[c]*Ve[l][c][h]
__global__ void k_fold(const float* __restrict__ Wg, const float* __restrict__ Weg,
                       const float* __restrict__ as_, const float* __restrict__ ad_,
                       const float* __restrict__ ae_, const float* __restrict__ Wep,
                       const float* __restrict__ bep) {
    int tid = threadIdx.x;
    for (int it = tid; it < NL * HD * 4; it += blockDim.x) {
        int l = it >> 9;
        int r = it & 511;
        int c = r >> 2;
        int h = r & 3;
        const float* w1 = Wg + ((size_t)(l * HD + c)) * 512 + h * HD;
        const float* w2 = Weg + ((size_t)(l * HD + c)) * 512 + h * HD;
        const float* a1 = as_ + (l * 4 + h) * HD;
        const float* a2 = ad_ + (l * 4 + h) * HD;
        const float* a3 = ae_ + (l * 4 + h) * HD;
        float s1 = 0.f, s2 = 0.f, s3 = 0.f;
        for (int k = 0; k < HD; k++) {
            float wv = w1[k];
            s1 += wv * a1[k];
            s2 += wv * a2[k];
            s3 += w2[k] * a3[k];
        }
        g_Vs[it] = s1; g_Vd[it] = s2; g_Ve[it] = s3;
    }
    __syncthreads();
    for (int it = tid; it < FE_DIM * 12; it += blockDim.x) {
        int f = it / 12; int j = it % 12; int l = j >> 2; int h = j & 3;
        float s = 0.f;
        for (int c = 0; c < HD; c++) s += Wep[f * HD + c] * g_Ve[(l * HD + c) * 4 + h];
        g_Fe[it] = s;
    }
    for (int it = tid; it < 12; it += blockDim.x) {
        int l = it >> 2; int h = it & 3;
        float s = 0.f;
        for (int c = 0; c < HD; c++) s += bep[c] * g_Ve[(l * HD + c) * 4 + h];
        g_be[it] = s;
    }
}

// Wb[l][h*128+c][c'] = 0.25 * W_gat[l][c][h*128+c']  (head-mean folded)
__global__ void k_wb(const float* __restrict__ Wg) {
    int i = blockIdx.x * blockDim.x + threadIdx.x;
    if (i >= NL * 512 * HD) return;
    int l = i / (512 * HD);
    int r = i % (512 * HD);
    int k = r / HD;
    int cp = r % HD;
    int h = k >> 7; int c = k & 127;
    g_Wb[i] = 0.25f * Wg[((size_t)(l * HD + c)) * 512 + h * HD + cp];
}

// ---------------- SGEMM: C[M,N] = A[M,K] @ B[K,N]; N==128 here, K multiple of 8 ----
#define BMT 128
#define BNT 128
#define BKT 8
#define TMT 8
#define TNT 8
__global__ __launch_bounds__(256) void sgemm_k(int M, int N, int K,
                                               const float* __restrict__ A,
                                               const float* __restrict__ B,
                                               float* __restrict__ C) {
    __shared__ alignas(16) float As[BKT][BMT];
    __shared__ alignas(16) float Bs[BKT][BNT];
    int bx = blockIdx.x, by = blockIdx.y;
    int tid = threadIdx.x;
    int tx = tid & 15, ty = tid >> 4;
    int arow = tid >> 1;
    int acol = (tid & 1) << 2;
    int brow = tid >> 5;
    int bcol = (tid & 31) << 2;
    int aRowG = by * BMT + arow;
    const float* Aptr = A + (size_t)aRowG * K;
    float acc[TMT][TNT];
#pragma unroll
    for (int i = 0; i < TMT; i++)
#pragma unroll
        for (int j = 0; j < TNT; j++) acc[i][j] = 0.f;

    for (int k0 = 0; k0 < K; k0 += BKT) {
        float4 av = make_float4(0.f, 0.f, 0.f, 0.f);
        if (aRowG < M) av = *(const float4*)(Aptr + k0 + acol);
        As[acol + 0][arow] = av.x;
        As[acol + 1][arow] = av.y;
        As[acol + 2][arow] = av.z;
        As[acol + 3][arow] = av.w;
        float4 bv = *(const float4*)(B + (size_t)(k0 + brow) * N + bx * BNT + bcol);
        *(float4*)&Bs[brow][bcol] = bv;
        __syncthreads();
#pragma unroll
        for (int kk = 0; kk < BKT; kk++) {
            float ra[TMT], rb[TNT];
            *(float4*)&ra[0] = *(const float4*)&As[kk][ty * TMT];
            *(float4*)&ra[4] = *(const float4*)&As[kk][ty * TMT + 4];
            *(float4*)&rb[0] = *(const float4*)&Bs[kk][tx * TNT];
            *(float4*)&rb[4] = *(const float4*)&Bs[kk][tx * TNT + 4];
#pragma unroll
            for (int i = 0; i < TMT; i++)
#pragma unroll
                for (int j = 0; j < TNT; j++) acc[i][j] += ra[i] * rb[j];
        }
        __syncthreads();
    }
#pragma unroll
    for (int i = 0; i < TMT; i++) {
        int r = by * BMT + ty * TMT + i;
        if (r < M) {
            float* cp = C + (size_t)r * N + bx * BNT + tx * TNT;
            *(float4*)cp = make_float4(acc[i][0], acc[i][1], acc[i][2], acc[i][3]);
            *(float4*)(cp + 4) = make_float4(acc[i][4], acc[i][5], acc[i][6], acc[i][7]);
        }
    }
}

// x = tmp + b_proj + type_table[nt]
__global__ void k_bias_type(const float* __restrict__ bp, const float* __restrict__ tt,
                            const int* __restrict__ nt) {
    int i = blockIdx.x * blockDim.x + threadIdx.x;
    if (i >= NN * HD) return;
    int n = i >> 7; int c = i & 127;
    g_x[i] = g_tmp[i] + bp[c] + tt[(size_t)nt[n] * HD + c];
}

// per-edge attention logits for all 3 layers x 4 heads, plus column sums for loop mean
__global__ __launch_bounds__(64) void k_alE(const float* __restrict__ ef) {
    __shared__ float sef[64][65];
    __shared__ float sFe[64 * 12];
    __shared__ float sbe[12];
    __shared__ float sred[64][12];
    int tid = threadIdx.x;
    int e0 = blockIdx.x * 64;
    for (int i = tid; i < 64 * 12; i += 64) sFe[i] = g_Fe[i];
    if (tid < 12) sbe[tid] = g_be[tid];
    for (int it = 0; it < 64; it++) {
        int e = e0 + it;
        sef[it][tid] = (e < EE) ? ef[(size_t)e * 64 + tid] : 0.f;
    }
    __syncthreads();
    float acc[12];
#pragma unroll
    for (int j = 0; j < 12; j++) acc[j] = sbe[j];
    for (int k = 0; k < 64; k++) {
        float xv = sef[tid][k];
#pragma unroll
        for (int j = 0; j < 12; j++) acc[j] += xv * sFe[k * 12 + j];
    }
    int e = e0 + tid;
    if (e < EE) {
#pragma unroll
        for (int j = 0; j < 12; j++) g_alE[(size_t)e * 12 + j] = acc[j];
    } else {
#pragma unroll
        for (int j = 0; j < 12; j++) acc[j] = 0.f;
    }
#pragma unroll
    for (int j = 0; j < 12; j++) sred[tid][j] = acc[j];
    __syncthreads();
    for (int s = 32; s > 0; s >>= 1) {
        if (tid < s) {
#pragma unroll
            for (int j = 0; j < 12; j++) sred[tid][j] += sred[tid + s][j];
        }
        __syncthreads();
    }
    if (tid < 12) atomicAdd(&g_alE_sum[tid], sred[0][tid]);
}

__global__ void k_loopval() {
    int tid = threadIdx.x;
    if (tid < 12) g_alE_loop[tid] = g_alE_sum[tid] * (1.f / (float)EE);
}

// ---------------- CSR build (by dst) ----------------
__global__ void k_deg(const int* __restrict__ dst) {
    int i = blockIdx.x * blockDim.x + threadIdx.x;
    if (i < EE) atomicAdd(&g_deg[dst[i]], 1);
}

__global__ __launch_bounds__(1024) void k_scan() {
    __shared__ int sm[1024];
    __shared__ int carry;
    int tid = threadIdx.x;
    if (tid == 0) carry = 0;
    __syncthreads();
    for (int base = 0; base < NN; base += 1024) {
        int i = base + tid;
        int v = (i < NN) ? g_deg[i] : 0;
        sm[tid] = v;
        __syncthreads();
        int total_prev = carry;
        for (int o = 1; o < 1024; o <<= 1) {
            int t = (tid >= o) ? sm[tid - o] : 0;
            __syncthreads();
            sm[tid] += t;
            __syncthreads();
        }
        if (i < NN) g_off[i] = total_prev + sm[tid] - v;
        __syncthreads();
        if (tid == 0) carry = total_prev + sm[1023];
        __syncthreads();
    }
    if (tid == 0) g_off[NN] = carry;
}

__global__ void k_cur() {
    int i = blockIdx.x * blockDim.x + threadIdx.x;
    if (i < NN) g_cur[i] = g_off[i];
}

__global__ void k_fill(const int* __restrict__ dst) {
    int i = blockIdx.x * blockDim.x + threadIdx.x;
    if (i < EE) {
        int p = atomicAdd(&g_cur[dst[i]], 1);
        g_eid[p] = i;
    }
}

// ---------------- per-layer: als/ald = x @ Vs/Vd (one warp per node) ----------------
__global__ __launch_bounds__(256) void k_alsald(int l) {
    int w = (blockIdx.x * blockDim.x + threadIdx.x) >> 5;
    int lane = threadIdx.x & 31;
    if (w >= NN) return;
    int n = w;
    float4 xv = *(const float4*)&g_x[(size_t)n * HD + lane * 4];
    float xs[4] = {xv.x, xv.y, xv.z, xv.w};
    const float* Vs = g_Vs + l * HD * 4;
    const float* Vd = g_Vd + l * HD * 4;
    float sa0 = 0, sa1 = 0, sa2 = 0, sa3 = 0;
    float da0 = 0, da1 = 0, da2 = 0, da3 = 0;
#pragma unroll
    for (int j = 0; j < 4; j++) {
        int c = lane * 4 + j;
        float4 vs = *(const float4*)&Vs[c * 4];
        float4 vd = *(const float4*)&Vd[c * 4];
        float x1 = xs[j];
        sa0 += x1 * vs.x; sa1 += x1 * vs.y; sa2 += x1 * vs.z; sa3 += x1 * vs.w;
        da0 += x1 * vd.x; da1 += x1 * vd.y; da2 += x1 * vd.z; da3 += x1 * vd.w;
    }
#pragma unroll
    for (int o = 16; o > 0; o >>= 1) {
        sa0 += __shfl_xor_sync(0xffffffffu, sa0, o);
        sa1 += __shfl_xor_sync(0xffffffffu, sa1, o);
        sa2 += __shfl_xor_sync(0xffffffffu, sa2, o);
        sa3 += __shfl_xor_sync(0xffffffffu, sa3, o);
        da0 += __shfl_xor_sync(0xffffffffu, da0, o);
        da1 += __shfl_xor_sync(0xffffffffu, da1, o);
        da2 += __shfl_xor_sync(0xffffffffu, da2, o);
        da3 += __shfl_xor_sync(0xffffffffu, da3, o);
    }
    if (lane == 0) {
        *(float4*)&g_als[n * 4] = make_float4(sa0, sa1, sa2, sa3);
        *(float4*)&g_ald[n * 4] = make_float4(da0, da1, da2, da3);
    }
}

__device__ __forceinline__ float lrelu(float a) { return (a > 0.f) ? a : 0.2f * a; }

// ---------------- fused GAT softmax + weighted gather (one warp per dst node) ------
__global__ __launch_bounds__(256) void k_gat_agg(int l, const int* __restrict__ src) {
    __shared__ alignas(16) float s_p[8][32][4];
    __shared__ int s_s[8][32];
    int wip = threadIdx.x >> 5;
    int lane = threadIdx.x & 31;
    int n = blockIdx.x * 8 + wip;
    if (n >= NN) return;
    int start = g_off[n], end = g_off[n + 1];
    float4 adn = *(const float4*)&g_ald[n * 4];
    float z0 = 0, z1 = 0, z2 = 0, z3 = 0;
    float acc[4][4];
#pragma unroll
    for (int h = 0; h < 4; h++)
#pragma unroll
        for (int j = 0; j < 4; j++) acc[h][j] = 0.f;

    for (int base = start; base < end; base += 32) {
        int j = base + lane;
        int cnt = min(32, end - base);
        if (j < end) {
            int e = g_eid[j];
            int s = src[e];
            s_s[wip][lane] = s;
            float4 ae = *(const float4*)&g_alE[(size_t)e * 12 + l * 4];
            float4 as = *(const float4*)&g_als[s * 4];
            float p0 = __expf(lrelu(as.x + adn.x + ae.x));
            float p1 = __expf(lrelu(as.y + adn.y + ae.y));
            float p2 = __expf(lrelu(as.z + adn.z + ae.z));
            float p3 = __expf(lrelu(as.w + adn.w + ae.w));
            s_p[wip][lane][0] = p0; s_p[wip][lane][1] = p1;
            s_p[wip][lane][2] = p2; s_p[wip][lane][3] = p3;
            z0 += p0; z1 += p1; z2 += p2; z3 += p3;
        }
        __syncwarp();
        for (int t = 0; t < cnt; t++) {
            int s = s_s[wip][t];
            float4 pv = *(const float4*)&s_p[wip][t][0];
            float4 xv = *(const float4*)&g_x[(size_t)s * HD + lane * 4];
            acc[0][0] += pv.x * xv.x; acc[0][1] += pv.x * xv.y; acc[0][2] += pv.x * xv.z; acc[0][3] += pv.x * xv.w;
            acc[1][0] += pv.y * xv.x; acc[1][1] += pv.y * xv.y; acc[1][2] += pv.y * xv.z; acc[1][3] += pv.y * xv.w;
            acc[2][0] += pv.z * xv.x; acc[2][1] += pv.z * xv.y; acc[2][2] += pv.z * xv.z; acc[2][3] += pv.z * xv.w;
            acc[3][0] += pv.w * xv.x; acc[3][1] += pv.w * xv.y; acc[3][2] += pv.w * xv.z; acc[3][3] += pv.w * xv.w;
        }
        __syncwarp();
    }
#pragma unroll
    for (int o = 16; o > 0; o >>= 1) {
        z0 += __shfl_xor_sync(0xffffffffu, z0, o);
        z1 += __shfl_xor_sync(0xffffffffu, z1, o);
        z2 += __shfl_xor_sync(0xffffffffu, z2, o);
        z3 += __shfl_xor_sync(0xffffffffu, z3, o);
    }
    // self loop
    float4 asn = *(const float4*)&g_als[n * 4];
    float4 aL = *(const float4*)&g_alE_loop[l * 4];
    float q0 = __expf(lrelu(asn.x + adn.x + aL.x));
    float q1 = __expf(lrelu(asn.y + adn.y + aL.y));
    float q2 = __expf(lrelu(asn.z + adn.z + aL.z));
    float q3 = __expf(lrelu(asn.w + adn.w + aL.w));
    z0 += q0; z1 += q1; z2 += q2; z3 += q3;
    float4 xn = *(const float4*)&g_x[(size_t)n * HD + lane * 4];
    acc[0][0] += q0 * xn.x; acc[0][1] += q0 * xn.y; acc[0][2] += q0 * xn.z; acc[0][3] += q0 * xn.w;
    acc[1][0] += q1 * xn.x; acc[1][1] += q1 * xn.y; acc[1][2] += q1 * xn.z; acc[1][3] += q1 * xn.w;
    acc[2][0] += q2 * xn.x; acc[2][1] += q2 * xn.y; acc[2][2] += q2 * xn.z; acc[2][3] += q2 * xn.w;
    acc[3][0] += q3 * xn.x; acc[3][1] += q3 * xn.y; acc[3][2] += q3 * xn.z; acc[3][3] += q3 * xn.w;
    float inv0 = 1.f / (z0 + 1e-16f);
    float inv1 = 1.f / (z1 + 1e-16f);
    float inv2 = 1.f / (z2 + 1e-16f);
    float inv3 = 1.f / (z3 + 1e-16f);
    float* o0 = &g_agg[(size_t)n * 512 + 0 * HD + lane * 4];
    float* o1 = &g_agg[(size_t)n * 512 + 1 * HD + lane * 4];
    float* o2 = &g_agg[(size_t)n * 512 + 2 * HD + lane * 4];
    float* o3 = &g_agg[(size_t)n * 512 + 3 * HD + lane * 4];
    *(float4*)o0 = make_float4(acc[0][0] * inv0, acc[0][1] * inv0, acc[0][2] * inv0, acc[0][3] * inv0);
    *(float4*)o1 = make_float4(acc[1][0] * inv1, acc[1][1] * inv1, acc[1][2] * inv1, acc[1][3] * inv1);
    *(float4*)o2 = make_float4(acc[2][0] * inv2, acc[2][1] * inv2, acc[2][2] * inv2, acc[2][3] * inv2);
    *(float4*)o3 = make_float4(acc[3][0] * inv3, acc[3][1] * inv3, acc[3][2] * inv3, acc[3][3] * inv3);
}

// ---------------- residual + layernorm + gelu (one warp per node) ----------------
__global__ __launch_bounds__(256) void k_post(const float* __restrict__ bias,
                                              const float* __restrict__ lng,
                                              const float* __restrict__ lnb) {
    int w = (blockIdx.x * blockDim.x + threadIdx.x) >> 5;
    int lane = threadIdx.x & 31;
    if (w >= NN) return;
    int n = w;
    float4 tv = *(const float4*)&g_tmp[(size_t)n * HD + lane * 4];
    float4 xo = *(const float4*)&g_x[(size_t)n * HD + lane * 4];
    float4 bv = *(const float4*)&bias[lane * 4];
    float y[4];
    y[0] = tv.x + bv.x + xo.x;
    y[1] = tv.y + bv.y + xo.y;
    y[2] = tv.z + bv.z + xo.z;
    y[3] = tv.w + bv.w + xo.w;
    float s = y[0] + y[1] + y[2] + y[3];
#pragma unroll
    for (int o = 16; o > 0; o >>= 1) s += __shfl_xor_sync(0xffffffffu, s, o);
    float mu = s * (1.f / 128.f);
    float v = 0.f;
#pragma unroll
    for (int j = 0; j < 4; j++) { float d = y[j] - mu; v += d * d; }
#pragma unroll
    for (int o = 16; o > 0; o >>= 1) v += __shfl_xor_sync(0xffffffffu, v, o);
    float rstd = rsqrtf(v * (1.f / 128.f) + 1e-5f);
    float4 gv = *(const float4*)&lng[lane * 4];
    float4 bb = *(const float4*)&lnb[lane * 4];
    float g4[4] = {gv.x, gv.y, gv.z, gv.w};
    float b4[4] = {bb.x, bb.y, bb.z, bb.w};
    float out[4];
#pragma unroll
    for (int j = 0; j < 4; j++) {
        float t = (y[j] - mu) * rstd * g4[j] + b4[j];
        out[j] = 0.5f * t * (1.f + erff(t * 0.70710678118654752f));
    }
    *(float4*)&g_x[(size_t)n * HD + lane * 4] = make_float4(out[0], out[1], out[2], out[3]);
}

// ---------------- output x copy ----------------
__global__ void k_copy_x(float* __restrict__ out) {
    int i = blockIdx.x * blockDim.x + threadIdx.x;
    if (i < NN * HD) out[i] = g_x[i];
}

// ---------------- graph boundaries via binary search on sorted batch ----------------
__global__ void k_bounds(const int* __restrict__ batch) {
    int b = threadIdx.x;
    if (b <= NB) {
        int lo = 0, hi = NN;
        while (lo < hi) {
            int mid = (lo + hi) >> 1;
            if (batch[mid] < b) lo = mid + 1; else hi = mid;
        }
        g_gs[b] = lo;
    }
}

// ---------------- pooling: one block per graph, deterministic segmented reduction ----
__global__ __launch_bounds__(128) void k_pool(const int* __restrict__ nt,
                                              float* __restrict__ out_emb) {
    int b = blockIdx.x;
    int t = threadIdx.x;
    int s = g_gs[b], e = g_gs[b + 1];
    float fn = 0.f, st = 0.f, ex = 0.f, gl = 0.f;
    for (int n = s; n < e; n++) {
        float v = g_x[(size_t)n * HD + t];
        int ty = nt[n];
        gl += v;
        if (ty <= 5) fn += v;
        else if (ty <= 20) st += v;
        else ex += v;
    }
    float cnt = (float)(e - s);
    if (cnt < 1.f) cnt = 1.f;
    float inv = 1.f / cnt;
    out_emb[b * 512 + t]       = fn * inv;
    out_emb[b * 512 + 128 + t] = st * inv;
    out_emb[b * 512 + 256 + t] = ex * inv;
    out_emb[b * 512 + 384 + t] = gl * inv;
}

// ---------------- host launch ----------------
extern "C" void kernel_launch(void* const* d_in, const int* in_sizes, int n_in,
                              void* d_out, int out_size) {
    const float* node_features = (const float*)d_in[0];
    const float* edge_features = (const float*)d_in[1];
    const int*   node_types    = (const int*)d_in[2];
    const int*   edge_index    = (const int*)d_in[3];
    const int*   batch         = (const int*)d_in[4];
    const float* W_proj        = (const float*)d_in[5];
    const float* b_proj        = (const float*)d_in[6];
    const float* type_table    = (const float*)d_in[7];
    const float* W_edgeproj    = (const float*)d_in[8];
    const float* b_edgeproj    = (const float*)d_in[9];
    const float* W_gat         = (const float*)d_in[10];
    const float* W_edge_gat    = (const float*)d_in[11];
    const float* att_src       = (const float*)d_in[12];
    const float* att_dst       = (const float*)d_in[13];
    const float* att_edge      = (const float*)d_in[14];
    const float* gat_bias      = (const float*)d_in[15];
    const float* ln_g          = (const float*)d_in[16];
    const float* ln_b          = (const float*)d_in[17];

    const int* src = edge_index;        // row 0
    const int* dst = edge_index + EE;   // row 1

    // CRITICAL: resolve real DEVICE addresses of the __device__ scratch arrays.
    // Passing the symbols directly from host code passes the host shadow address,
    // which on GB300 (ATS) the GPU silently dereferences via NVLink-C2C -> garbage.
    float *p_tmp = 0, *p_agg = 0, *p_wb = 0;
    cudaGetSymbolAddress((void**)&p_tmp, g_tmp);
    cudaGetSymbolAddress((void**)&p_agg, g_agg);
    cudaGetSymbolAddress((void**)&p_wb,  g_Wb);

    float* out = (float*)d_out;
    // Output layout: tuple (x, graph_embedding) flattened & concatenated.
    float* out_x = out;
    float* out_emb = 0;
    bool write_x = true, write_emb = true;
    if (out_size >= NN * HD + NB * 512) {
        out_emb = out + NN * HD;
    } else if (out_size == NB * 512) {
        out_emb = out;
        write_x = false;
    } else {
        // only x fits: never alias the emb write over x
        write_emb = false;
    }

    k_init<<<(NN + 255) / 256, 256>>>();
    k_fold<<<1, 256>>>(W_gat, W_edge_gat, att_src, att_dst, att_edge, W_edgeproj, b_edgeproj);
    k_wb<<<(NL * 512 * HD + 255) / 256, 256>>>(W_gat);

    // CSR by dst
    k_deg<<<(EE + 255) / 256, 256>>>(dst);
    k_scan<<<1, 1024>>>();
    k_cur<<<(NN + 255) / 256, 256>>>();
    k_fill<<<(EE + 255) / 256, 256>>>(dst);

    // edge logits (all layers at once) + self-loop mean
    k_alE<<<(EE + 63) / 64, 64>>>(edge_features);
    k_loopval<<<1, 32>>>();

    // initial projection + bias + type embedding
    {
        dim3 grid(1, (NN + BMT - 1) / BMT);
        sgemm_k<<<grid, 256>>>(NN, HD, HD, node_features, W_proj, p_tmp);
    }
    k_bias_type<<<(NN * HD + 255) / 256, 256>>>(b_proj, type_table, node_types);

    for (int l = 0; l < NL; l++) {
        k_alsald<<<(NN * 32 + 255) / 256, 256>>>(l);
        k_gat_agg<<<(NN + 7) / 8, 256>>>(l, src);
        dim3 grid(1, (NN + BMT - 1) / BMT);
        sgemm_k<<<grid, 256>>>(NN, HD, 512, p_agg, p_wb + (size_t)l * 512 * HD, p_tmp);
        k_post<<<(NN * 32 + 255) / 256, 256>>>(gat_bias + l * HD, ln_g + l * HD, ln_b + l * HD);
    }

    if (write_x) k_copy_x<<<(NN * HD + 255) / 256, 256>>>(out_x);
    if (write_emb) {
        k_bounds<<<1, 32>>>(batch);
        k_pool<<<NB, 128>>>(node_types, out_emb);
    }
}

// round 9
// speedup vs baseline: 1.0024x; 1.0024x over previous
#include <cuda_runtime.h>
#include <math.h>

#define NN 50000
#define EE 400000
#define FE_DIM 64
#define HD 128
#define NL 3
#define NB 16

// ---------------- scratch (static device globals; no allocation) ----------------
__device__ alignas(16) float g_x[NN * HD];             // node features (updated per layer)
__device__ alignas(16) float g_tmp[NN * HD];           // GEMM outputs
__device__ alignas(16) float g_agg[NN * 4 * HD];       // per-head aggregated x (input space)
__device__ alignas(16) float g_alE[EE * 12];           // per-edge attention logits, 3 layers x 4 heads
__device__ alignas(16) float g_alE_sum[12];
__device__ alignas(16) float g_alE_loop[12];           // self-loop edge logits (mean over E)
__device__ alignas(16) float g_als[NN * 4];
__device__ alignas(16) float g_ald[NN * 4];
__device__ int g_deg[NN];
__device__ int g_off[NN + 1];
__device__ int g_cur[NN];
__device__ int g_eid[EE];
__device__ int g_gs[NB + 1];
__device__ alignas(16) float g_Vs[NL * HD * 4];
__device__ alignas(16) float g_Vd[NL * HD * 4];
__device__ alignas(16) float g_Ve[NL * HD * 4];
__device__ alignas(16) float g_Fe[FE_DIM * 12];
__device__ alignas(16) float g_be[12];
__device__ alignas(16) float g_Wb[NL * 512 * HD];      // 0.25 * W_gat, reindexed [k=h*128+c][c']

// ---- packed fp32x2 helpers (sm_103a dual-FMA path; ptxas never emits from C++) ----
#define DUP2(d, f)    asm("mov.b64 %0, {%1, %1};" : "=l"(d) : "r"(__float_as_uint(f)))
#define FMA2(d, a, b) asm("fma.rn.f32x2 %0, %1, %2, %0;" : "+l"(d) : "l"(a), "l"(b))
#define UNPK2(lo, hi, d) asm("mov.b64 {%0, %1}, %2;" : "=r"(lo), "=r"(hi) : "l"(d))

// ---------------- init ----------------
__global__ void k_init() {
    int i = blockIdx.x * blockDim.x + threadIdx.x;
    if (i < NN) g_deg[i] = 0;
    if (i < 12) g_alE_sum[i] = 0.f;
}

// ---------------- fold attention vectors ----------------
__global__ void k_fold(const float* __restrict__ Wg, const float* __restrict__ Weg,
                       const float* __restrict__ as_, const float* __restrict__ ad_,
                       const float* __restrict__ ae_, const float* __restrict__ Wep,
                       const float* __restrict__ bep) {
    int tid = threadIdx.x;
    for (int it = tid; it < NL * HD * 4; it += blockDim.x) {
        int l = it >> 9;
        int r = it & 511;
        int c = r >> 2;
        int h = r & 3;
        const float* w1 = Wg + ((size_t)(l * HD + c)) * 512 + h * HD;
        const float* w2 = Weg + ((size_t)(l * HD + c)) * 512 + h * HD;
        const float* a1 = as_ + (l * 4 + h) * HD;
        const float* a2 = ad_ + (l * 4 + h) * HD;
        const float* a3 = ae_ + (l * 4 + h) * HD;
        float s1 = 0.f, s2 = 0.f, s3 = 0.f;
        for (int k = 0; k < HD; k++) {
            float wv = w1[k];
            s1 += wv * a1[k];
            s2 += wv * a2[k];
            s3 += w2[k] * a3[k];
        }
        g_Vs[it] = s1; g_Vd[it] = s2; g_Ve[it] = s3;
    }
    __syncthreads();
    for (int it = tid; it < FE_DIM * 12; it += blockDim.x) {
        int f = it / 12; int j = it % 12; int l = j >> 2; int h = j & 3;
        float s = 0.f;
        for (int c = 0; c < HD; c++) s += Wep[f * HD + c] * g_Ve[(l * HD + c) * 4 + h];
        g_Fe[it] = s;
    }
    for (int it = tid; it < 12; it += blockDim.x) {
        int l = it >> 2; int h = it & 3;
        float s = 0.f;
        for (int c = 0; c < HD; c++) s += bep[c] * g_Ve[(l * HD + c) * 4 + h];
        g_be[it] = s;
    }
}

// Wb[l][h*128+c][c'] = 0.25 * W_gat[l][c][h*128+c']  (head-mean folded)
__global__ void k_wb(const float* __restrict__ Wg) {
    int i = blockIdx.x * blockDim.x + threadIdx.x;
    if (i >= NL * 512 * HD) return;
    int l = i / (512 * HD);
    int r = i % (512 * HD);
    int k = r / HD;
    int cp = r % HD;
    int h = k >> 7; int c = k & 127;
    g_Wb[i] = 0.25f * Wg[((size_t)(l * HD + c)) * 512 + h * HD + cp];
}

// ---------------- SGEMM (f32x2, double-buffered): C[M,128] = A[M,K] @ B[K,128] ----
#define BM 128
#define BK 8
__global__ __launch_bounds__(256) void sgemm2_k(int M, int K,
                                                const float* __restrict__ A,
                                                const float* __restrict__ B,
                                                float* __restrict__ C) {
    __shared__ alignas(16) float As[2][BK][BM];
    __shared__ alignas(16) float Bs[2][BK][128];
    int tid = threadIdx.x;
    int by = blockIdx.y;
    int tx = tid & 15, ty = tid >> 4;         // 16 x 16 thread grid; 8x8 outputs each
    int arow = tid >> 1;
    int acol = (tid & 1) << 2;
    int brow = tid >> 5;
    int bcol = (tid & 31) << 2;
    int aRowG = by * BM + arow;
    bool arow_ok = aRowG < M;
    const float* Aptr = A + (size_t)aRowG * K;

    unsigned long long acc2[8][4];            // 8 M-rows x 4 N-pairs (8 cols)
#pragma unroll
    for (int i = 0; i < 8; i++)
#pragma unroll
        for (int j = 0; j < 4; j++) acc2[i][j] = 0ull;

    // preload tile 0
    {
        float4 av = make_float4(0.f, 0.f, 0.f, 0.f);
        if (arow_ok) av = *(const float4*)(Aptr + acol);
        As[0][acol + 0][arow] = av.x;
        As[0][acol + 1][arow] = av.y;
        As[0][acol + 2][arow] = av.z;
        As[0][acol + 3][arow] = av.w;
        float4 bv = *(const float4*)(B + (size_t)brow * 128 + bcol);
        *(float4*)&Bs[0][brow][bcol] = bv;
    }
    __syncthreads();

    int nk = K / BK;
    for (int kb = 0; kb < nk; kb++) {
        int buf = kb & 1;
        // prefetch next tile into the other buffer (single barrier per iter:
        // nbuf was last read before the barrier at end of previous iteration)
        if (kb + 1 < nk) {
            int k0 = (kb + 1) * BK;
            float4 av = make_float4(0.f, 0.f, 0.f, 0.f);
            if (arow_ok) av = *(const float4*)(Aptr + k0 + acol);
            float4 bv = *(const float4*)(B + (size_t)(k0 + brow) * 128 + bcol);
            int nb = buf ^ 1;
            As[nb][acol + 0][arow] = av.x;
            As[nb][acol + 1][arow] = av.y;
            As[nb][acol + 2][arow] = av.z;
            As[nb][acol + 3][arow] = av.w;
            *(float4*)&Bs[nb][brow][bcol] = bv;
        }
#pragma unroll
        for (int kk = 0; kk < BK; kk++) {
            float ra[8];
            *(float4*)&ra[0] = *(const float4*)&As[buf][kk][ty * 8];
            *(float4*)&ra[4] = *(const float4*)&As[buf][kk][ty * 8 + 4];
            ulonglong2 bq0 = *(const ulonglong2*)&Bs[buf][kk][tx * 8];
            ulonglong2 bq1 = *(const ulonglong2*)&Bs[buf][kk][tx * 8 + 4];
            unsigned long long b0 = bq0.x, b1 = bq0.y, b2 = bq1.x, b3 = bq1.y;
#pragma unroll
            for (int i = 0; i < 8; i++) {
                unsigned long long a2;
                DUP2(a2, ra[i]);
                FMA2(acc2[i][0], a2, b0);
                FMA2(acc2[i][1], a2, b1);
                FMA2(acc2[i][2], a2, b2);
                FMA2(acc2[i][3], a2, b3);
            }
        }
        __syncthreads();
    }

#pragma unroll
    for (int i = 0; i < 8; i++) {
        int r = by * BM + ty * 8 + i;
        if (r < M) {
            float o[8];
#pragma unroll
            for (int j = 0; j < 4; j++) {
                unsigned int lo, hi;
                UNPK2(lo, hi, acc2[i][j]);
                o[2 * j] = __uint_as_float(lo);
                o[2 * j + 1] = __uint_as_float(hi);
            }
            float* cp = C + (size_t)r * 128 + tx * 8;
            *(float4*)cp = make_float4(o[0], o[1], o[2], o[3]);
            *(float4*)(cp + 4) = make_float4(o[4], o[5], o[6], o[7]);
        }
    }
}

// x = tmp + b_proj + type_table[nt]
__global__ void k_bias_type(const float* __restrict__ bp, const float* __restrict__ tt,
                            const int* __restrict__ nt) {
    int i = blockIdx.x * blockDim.x + threadIdx.x;
    if (i >= NN * HD) return;
    int n = i >> 7; int c = i & 127;
    g_x[i] = g_tmp[i] + bp[c] + tt[(size_t)nt[n] * HD + c];
}

// per-edge attention logits for all 3 layers x 4 heads, plus column sums for loop mean
__global__ __launch_bounds__(64) void k_alE(const float* __restrict__ ef) {
    __shared__ float sef[64][65];
    __shared__ float sFe[64 * 12];
    __shared__ float sbe[12];
    __shared__ float sred[64][12];
    int tid = threadIdx.x;
    int e0 = blockIdx.x * 64;
    for (int i = tid; i < 64 * 12; i += 64) sFe[i] = g_Fe[i];
    if (tid < 12) sbe[tid] = g_be[tid];
    for (int it = 0; it < 64; it++) {
        int e = e0 + it;
        sef[it][tid] = (e < EE) ? ef[(size_t)e * 64 + tid] : 0.f;
    }
    __syncthreads();
    float acc[12];
#pragma unroll
    for (int j = 0; j < 12; j++) acc[j] = sbe[j];
    for (int k = 0; k < 64; k++) {
        float xv = sef[tid][k];
#pragma unroll
        for (int j = 0; j < 12; j++) acc[j] += xv * sFe[k * 12 + j];
    }
    int e = e0 + tid;
    if (e < EE) {
#pragma unroll
        for (int j = 0; j < 12; j++) g_alE[(size_t)e * 12 + j] = acc[j];
    } else {
#pragma unroll
        for (int j = 0; j < 12; j++) acc[j] = 0.f;
    }
#pragma unroll
    for (int j = 0; j < 12; j++) sred[tid][j] = acc[j];
    __syncthreads();
    for (int s = 32; s > 0; s >>= 1) {
        if (tid < s) {
#pragma unroll
            for (int j = 0; j < 12; j++) sred[tid][j] += sred[tid + s][j];
        }
        __syncthreads();
    }
    if (tid < 12) atomicAdd(&g_alE_sum[tid], sred[0][tid]);
}

__global__ void k_loopval() {
    int tid = threadIdx.x;
    if (tid < 12) g_alE_loop[tid] = g_alE_sum[tid] * (1.f / (float)EE);
}

// ---------------- CSR build (by dst) ----------------
__global__ void k_deg(const int* __restrict__ dst) {
    int i = blockIdx.x * blockDim.x + threadIdx.x;
    if (i < EE) atomicAdd(&g_deg[dst[i]], 1);
}

__global__ __launch_bounds__(1024) void k_scan() {
    __shared__ int sm[1024];
    __shared__ int carry;
    int tid = threadIdx.x;
    if (tid == 0) carry = 0;
    __syncthreads();
    for (int base = 0; base < NN; base += 1024) {
        int i = base + tid;
        int v = (i < NN) ? g_deg[i] : 0;
        sm[tid] = v;
        __syncthreads();
        int total_prev = carry;
        for (int o = 1; o < 1024; o <<= 1) {
            int t = (tid >= o) ? sm[tid - o] : 0;
            __syncthreads();
            sm[tid] += t;
            __syncthreads();
        }
        if (i < NN) g_off[i] = total_prev + sm[tid] - v;
        __syncthreads();
        if (tid == 0) carry = total_prev + sm[1023];
        __syncthreads();
    }
    if (tid == 0) g_off[NN] = carry;
}

__global__ void k_cur() {
    int i = blockIdx.x * blockDim.x + threadIdx.x;
    if (i < NN) g_cur[i] = g_off[i];
}

__global__ void k_fill(const int* __restrict__ dst) {
    int i = blockIdx.x * blockDim.x + threadIdx.x;
    if (i < EE) {
        int p = atomicAdd(&g_cur[dst[i]], 1);
        g_eid[p] = i;
    }
}

// ---------------- per-layer: als/ald = x @ Vs/Vd (one warp per node) ----------------
__global__ __launch_bounds__(256) void k_alsald(int l) {
    int w = (blockIdx.x * blockDim.x + threadIdx.x) >> 5;
    int lane = threadIdx.x & 31;
    if (w >= NN) return;
    int n = w;
    float4 xv = *(const float4*)&g_x[(size_t)n * HD + lane * 4];
    float xs[4] = {xv.x, xv.y, xv.z, xv.w};
    const float* Vs = g_Vs + l * HD * 4;
    const float* Vd = g_Vd + l * HD * 4;
    float sa0 = 0, sa1 = 0, sa2 = 0, sa3 = 0;
    float da0 = 0, da1 = 0, da2 = 0, da3 = 0;
#pragma unroll
    for (int j = 0; j < 4; j++) {
        int c = lane * 4 + j;
        float4 vs = *(const float4*)&Vs[c * 4];
        float4 vd = *(const float4*)&Vd[c * 4];
        float x1 = xs[j];
        sa0 += x1 * vs.x; sa1 += x1 * vs.y; sa2 += x1 * vs.z; sa3 += x1 * vs.w;
        da0 += x1 * vd.x; da1 += x1 * vd.y; da2 += x1 * vd.z; da3 += x1 * vd.w;
    }
#pragma unroll
    for (int o = 16; o > 0; o >>= 1) {
        sa0 += __shfl_xor_sync(0xffffffffu, sa0, o);
        sa1 += __shfl_xor_sync(0xffffffffu, sa1, o);
        sa2 += __shfl_xor_sync(0xffffffffu, sa2, o);
        sa3 += __shfl_xor_sync(0xffffffffu, sa3, o);
        da0 += __shfl_xor_sync(0xffffffffu, da0, o);
        da1 += __shfl_xor_sync(0xffffffffu, da1, o);
        da2 += __shfl_xor_sync(0xffffffffu, da2, o);
        da3 += __shfl_xor_sync(0xffffffffu, da3, o);
    }
    if (lane == 0) {
        *(float4*)&g_als[n * 4] = make_float4(sa0, sa1, sa2, sa3);
        *(float4*)&g_ald[n * 4] = make_float4(da0, da1, da2, da3);
    }
}

__device__ __forceinline__ float lrelu(float a) { return (a > 0.f) ? a : 0.2f * a; }

// ---------------- fused GAT softmax + weighted gather (one warp per dst node) ------
__global__ __launch_bounds__(256) void k_gat_agg(int l, const int* __restrict__ src) {
    __shared__ alignas(16) float s_p[8][32][4];
    __shared__ int s_s[8][32];
    int wip = threadIdx.x >> 5;
    int lane = threadIdx.x & 31;
    int n = blockIdx.x * 8 + wip;
    if (n >= NN) return;
    int start = g_off[n], end = g_off[n + 1];
    float4 adn = *(const float4*)&g_ald[n * 4];
    float z0 = 0, z1 = 0, z2 = 0, z3 = 0;
    float acc[4][4];
#pragma unroll
    for (int h = 0; h < 4; h++)
#pragma unroll
        for (int j = 0; j < 4; j++) acc[h][j] = 0.f;

    for (int base = start; base < end; base += 32) {
        int j = base + lane;
        int cnt = min(32, end - base);
        if (j < end) {
            int e = g_eid[j];
            int s = src[e];
            s_s[wip][lane] = s;
            float4 ae = *(const float4*)&g_alE[(size_t)e * 12 + l * 4];
            float4 as = *(const float4*)&g_als[s * 4];
            float p0 = __expf(lrelu(as.x + adn.x + ae.x));
            float p1 = __expf(lrelu(as.y + adn.y + ae.y));
            float p2 = __expf(lrelu(as.z + adn.z + ae.z));
            float p3 = __expf(lrelu(as.w + adn.w + ae.w));
            s_p[wip][lane][0] = p0; s_p[wip][lane][1] = p1;
            s_p[wip][lane][2] = p2; s_p[wip][lane][3] = p3;
            z0 += p0; z1 += p1; z2 += p2; z3 += p3;
        }
        __syncwarp();
        for (int t = 0; t < cnt; t++) {
            int s = s_s[wip][t];
            float4 pv = *(const float4*)&s_p[wip][t][0];
            float4 xv = *(const float4*)&g_x[(size_t)s * HD + lane * 4];
            acc[0][0] += pv.x * xv.x; acc[0][1] += pv.x * xv.y; acc[0][2] += pv.x * xv.z; acc[0][3] += pv.x * xv.w;
            acc[1][0] += pv.y * xv.x; acc[1][1] += pv.y * xv.y; acc[1][2] += pv.y * xv.z; acc[1][3] += pv.y * xv.w;
            acc[2][0] += pv.z * xv.x; acc[2][1] += pv.z * xv.y; acc[2][2] += pv.z * xv.z; acc[2][3] += pv.z * xv.w;
            acc[3][0] += pv.w * xv.x; acc[3][1] += pv.w * xv.y; acc[3][2] += pv.w * xv.z; acc[3][3] += pv.w * xv.w;
        }
        __syncwarp();
    }
#pragma unroll
    for (int o = 16; o > 0; o >>= 1) {
        z0 += __shfl_xor_sync(0xffffffffu, z0, o);
        z1 += __shfl_xor_sync(0xffffffffu, z1, o);
        z2 += __shfl_xor_sync(0xffffffffu, z2, o);
        z3 += __shfl_xor_sync(0xffffffffu, z3, o);
    }
    // self loop
    float4 asn = *(const float4*)&g_als[n * 4];
    float4 aL = *(const float4*)&g_alE_loop[l * 4];
    float q0 = __expf(lrelu(asn.x + adn.x + aL.x));
    float q1 = __expf(lrelu(asn.y + adn.y + aL.y));
    float q2 = __expf(lrelu(asn.z + adn.z + aL.z));
    float q3 = __expf(lrelu(asn.w + adn.w + aL.w));
    z0 += q0; z1 += q1; z2 += q2; z3 += q3;
    float4 xn = *(const float4*)&g_x[(size_t)n * HD + lane * 4];
    acc[0][0] += q0 * xn.x; acc[0][1] += q0 * xn.y; acc[0][2] += q0 * xn.z; acc[0][3] += q0 * xn.w;
    acc[1][0] += q1 * xn.x; acc[1][1] += q1 * xn.y; acc[1][2] += q1 * xn.z; acc[1][3] += q1 * xn.w;
    acc[2][0] += q2 * xn.x; acc[2][1] += q2 * xn.y; acc[2][2] += q2 * xn.z; acc[2][3] += q2 * xn.w;
    acc[3][0] += q3 * xn.x; acc[3][1] += q3 * xn.y; acc[3][2] += q3 * xn.z; acc[3][3] += q3 * xn.w;
    float inv0 = 1.f / (z0 + 1e-16f);
    float inv1 = 1.f / (z1 + 1e-16f);
    float inv2 = 1.f / (z2 + 1e-16f);
    float inv3 = 1.f / (z3 + 1e-16f);
    float* o0 = &g_agg[(size_t)n * 512 + 0 * HD + lane * 4];
    float* o1 = &g_agg[(size_t)n * 512 + 1 * HD + lane * 4];
    float* o2 = &g_agg[(size_t)n * 512 + 2 * HD + lane * 4];
    float* o3 = &g_agg[(size_t)n * 512 + 3 * HD + lane * 4];
    *(float4*)o0 = make_float4(acc[0][0] * inv0, acc[0][1] * inv0, acc[0][2] * inv0, acc[0][3] * inv0);
    *(float4*)o1 = make_float4(acc[1][0] * inv1, acc[1][1] * inv1, acc[1][2] * inv1, acc[1][3] * inv1);
    *(float4*)o2 = make_float4(acc[2][0] * inv2, acc[2][1] * inv2, acc[2][2] * inv2, acc[2][3] * inv2);
    *(float4*)o3 = make_float4(acc[3][0] * inv3, acc[3][1] * inv3, acc[3][2] * inv3, acc[3][3] * inv3);
}

// ---------------- residual + layernorm + gelu (one warp per node) ----------------
__global__ __launch_bounds__(256) void k_post(const float* __restrict__ bias,
                                              const float* __restrict__ lng,
                                              const float* __restrict__ lnb) {
    int w = (blockIdx.x * blockDim.x + threadIdx.x) >> 5;
    int lane = threadIdx.x & 31;
    if (w >= NN) return;
    int n = w;
    float4 tv = *(const float4*)&g_tmp[(size_t)n * HD + lane * 4];
    float4 xo = *(const float4*)&g_x[(size_t)n * HD + lane * 4];
    float4 bv = *(const float4*)&bias[lane * 4];
    float y[4];
    y[0] = tv.x + bv.x + xo.x;
    y[1] = tv.y + bv.y + xo.y;
    y[2] = tv.z + bv.z + xo.z;
    y[3] = tv.w + bv.w + xo.w;
    float s = y[0] + y[1] + y[2] + y[3];
#pragma unroll
    for (int o = 16; o > 0; o >>= 1) s += __shfl_xor_sync(0xffffffffu, s, o);
    float mu = s * (1.f / 128.f);
    float v = 0.f;
#pragma unroll
    for (int j = 0; j < 4; j++) { float d = y[j] - mu; v += d * d; }
#pragma unroll
    for (int o = 16; o > 0; o >>= 1) v += __shfl_xor_sync(0xffffffffu, v, o);
    float rstd = rsqrtf(v * (1.f / 128.f) + 1e-5f);
    float4 gv = *(const float4*)&lng[lane * 4];
    float4 bb = *(const float4*)&lnb[lane * 4];
    float g4[4] = {gv.x, gv.y, gv.z, gv.w};
    float b4[4] = {bb.x, bb.y, bb.z, bb.w};
    float out[4];
#pragma unroll
    for (int j = 0; j < 4; j++) {
        float t = (y[j] - mu) * rstd * g4[j] + b4[j];
        out[j] = 0.5f * t * (1.f + erff(t * 0.70710678118654752f));
    }
    *(float4*)&g_x[(size_t)n * HD + lane * 4] = make_float4(out[0], out[1], out[2], out[3]);
}

// ---------------- output x copy ----------------
__global__ void k_copy_x(float* __restrict__ out) {
    int i = blockIdx.x * blockDim.x + threadIdx.x;
    if (i < NN * HD) out[i] = g_x[i];
}

// ---------------- graph boundaries via binary search on sorted batch ----------------
__global__ void k_bounds(const int* __restrict__ batch) {
    int b = threadIdx.x;
    if (b <= NB) {
        int lo = 0, hi = NN;
        while (lo < hi) {
            int mid = (lo + hi) >> 1;
            if (batch[mid] < b) lo = mid + 1; else hi = mid;
        }
        g_gs[b] = lo;
    }
}

// ---------------- pooling: one block per graph, deterministic segmented reduction ----
__global__ __launch_bounds__(128) void k_pool(const int* __restrict__ nt,
                                              float* __restrict__ out_emb) {
    int b = blockIdx.x;
    int t = threadIdx.x;
    int s = g_gs[b], e = g_gs[b + 1];
    float fn = 0.f, st = 0.f, ex = 0.f, gl = 0.f;
    for (int n = s; n < e; n++) {
        float v = g_x[(size_t)n * HD + t];
        int ty = nt[n];
        gl += v;
        if (ty <= 5) fn += v;
        else if (ty <= 20) st += v;
        else ex += v;
    }
    float cnt = (float)(e - s);
    if (cnt < 1.f) cnt = 1.f;
    float inv = 1.f / cnt;
    out_emb[b * 512 + t]       = fn * inv;
    out_emb[b * 512 + 128 + t] = st * inv;
    out_emb[b * 512 + 256 + t] = ex * inv;
    out_emb[b * 512 + 384 + t] = gl * inv;
}

// ---------------- host launch ----------------
extern "C" void kernel_launch(void* const* d_in, const int* in_sizes, int n_in,
                              void* d_out, int out_size) {
    const float* node_features = (const float*)d_in[0];
    const float* edge_features = (const float*)d_in[1];
    const int*   node_types    = (const int*)d_in[2];
    const int*   edge_index    = (const int*)d_in[3];
    const int*   batch         = (const int*)d_in[4];
    const float* W_proj        = (const float*)d_in[5];
    const float* b_proj        = (const float*)d_in[6];
    const float* type_table    = (const float*)d_in[7];
    const float* W_edgeproj    = (const float*)d_in[8];
    const float* b_edgeproj    = (const float*)d_in[9];
    const float* W_gat         = (const float*)d_in[10];
    const float* W_edge_gat    = (const float*)d_in[11];
    const float* att_src       = (const float*)d_in[12];
    const float* att_dst       = (const float*)d_in[13];
    const float* att_edge      = (const float*)d_in[14];
    const float* gat_bias      = (const float*)d_in[15];
    const float* ln_g          = (const float*)d_in[16];
    const float* ln_b          = (const float*)d_in[17];

    const int* src = edge_index;        // row 0
    const int* dst = edge_index + EE;   // row 1

    // Resolve real DEVICE addresses of __device__ scratch (host shadow would be
    // silently dereferenced over NVLink-C2C on GB300/ATS).
    float *p_tmp = 0, *p_agg = 0, *p_wb = 0;
    cudaGetSymbolAddress((void**)&p_tmp, g_tmp);
    cudaGetSymbolAddress((void**)&p_agg, g_agg);
    cudaGetSymbolAddress((void**)&p_wb,  g_Wb);

    float* out = (float*)d_out;
    // Output layout: tuple (x, graph_embedding) flattened & concatenated.
    float* out_x = out;
    float* out_emb = 0;
    bool write_x = true, write_emb = true;
    if (out_size >= NN * HD + NB * 512) {
        out_emb = out + NN * HD;
    } else if (out_size == NB * 512) {
        out_emb = out;
        write_x = false;
    } else {
        write_emb = false;
    }

    k_init<<<(NN + 255) / 256, 256>>>();
    k_fold<<<1, 256>>>(W_gat, W_edge_gat, att_src, att_dst, att_edge, W_edgeproj, b_edgeproj);
    k_wb<<<(NL * 512 * HD + 255) / 256, 256>>>(W_gat);

    // CSR by dst
    k_deg<<<(EE + 255) / 256, 256>>>(dst);
    k_scan<<<1, 1024>>>();
    k_cur<<<(NN + 255) / 256, 256>>>();
    k_fill<<<(EE + 255) / 256, 256>>>(dst);

    // edge logits (all layers at once) + self-loop mean
    k_alE<<<(EE + 63) / 64, 64>>>(edge_features);
    k_loopval<<<1, 32>>>();

    // initial projection + bias + type embedding
    {
        dim3 grid(1, (NN + BM - 1) / BM);
        sgemm2_k<<<grid, 256>>>(NN, HD, node_features, W_proj, p_tmp);
    }
    k_bias_type<<<(NN * HD + 255) / 256, 256>>>(b_proj, type_table, node_types);

    for (int l = 0; l < NL; l++) {
        k_alsald<<<(NN * 32 + 255) / 256, 256>>>(l);
        k_gat_agg<<<(NN + 7) / 8, 256>>>(l, src);
        dim3 grid(1, (NN + BM - 1) / BM);
        sgemm2_k<<<grid, 256>>>(NN, 512, p_agg, p_wb + (size_t)l * 512 * HD, p_tmp);
        k_post<<<(NN * 32 + 255) / 256, 256>>>(gat_bias + l * HD, ln_g + l * HD, ln_b + l * HD);
    }

    if (write_x) k_copy_x<<<(NN * HD + 255) / 256, 256>>>(out_x);
    if (write_emb) {
        k_bounds<<<1, 32>>>(batch);
        k_pool<<<NB, 128>>>(node_types, out_emb);
    }
}